// round 13
// baseline (speedup 1.0000x reference)
#include <cuda_runtime.h>
#include <cstddef>

// ---------------------------------------------------------------------------
// GCN_41128606826857: 3-layer GCN, N=50000, E=800000, 128 -> 96 -> 96 -> 64
// Inputs (metadata order):
//  0 x[N,128] f32, 1 edge_index[2,E] **int32** (JAX x64 disabled demotes the
//    requested int64 to int32!), 2 edge_weight[E] f32,
//  3 W1[96,128], 4 b1[96], 5 W2[96,96], 6 b2[96], 7 W3[64,96], 8 b3[64],
//  9 g1,10 beta1,11 m1,12 v1 (96 each), 13 g2,14 beta2,15 m2,16 v2 (96 each)
// Output: [N,64] f32
//
// Scratch: __device__ globals accessed through a device pointer table filled
// by k_setup (generic-pointer LDG/STG/RED). No runtime API in kernel_launch,
// no atomics into harness-owned d_out (plain stores only).
// ---------------------------------------------------------------------------

#define NMAX 50000
#define EMAX 800000
#define BN_EPS 1e-5f

__device__ float g_dinv[NMAX];       // degree -> rsqrt(degree)
__device__ float g_norm[EMAX];       // per-edge norm
__device__ float g_bufA[NMAX * 96];
__device__ float g_bufB[NMAX * 96];
__device__ float* g_ptr[4];          // 0:dinv 1:norm 2:bufA 3:bufB

// Idempotent, deterministic: safe to run every kernel_launch call.
__global__ void k_setup() {
    g_ptr[0] = g_dinv;
    g_ptr[1] = g_norm;
    g_ptr[2] = g_bufA;
    g_ptr[3] = g_bufB;
}

// ---------------------------------------------------------------------------
// gcn_norm pipeline
// ---------------------------------------------------------------------------
__global__ void k_deg_init(int n) {
    float* deg = g_ptr[0];
    int i = blockIdx.x * blockDim.x + threadIdx.x;
    if (i < n) deg[i] = 1.0f;  // self-loop weight
}

__global__ void k_deg_acc(const int* __restrict__ ei,
                          const float* __restrict__ ew, int e) {
    float* deg = g_ptr[0];
    int i = blockIdx.x * blockDim.x + threadIdx.x;
    if (i < e) {
        int c = ei[e + i];  // targets (second row of edge_index)
        atomicAdd(deg + c, ew[i]);
    }
}

__global__ void k_rsqrt_inplace(int n) {
    float* deg = g_ptr[0];
    int i = blockIdx.x * blockDim.x + threadIdx.x;
    if (i < n) {
        float v = deg[i];
        deg[i] = (v > 0.f) ? rsqrtf(v) : 0.f;
    }
}

__global__ void k_norm(const int* __restrict__ ei,
                       const float* __restrict__ ew, int e) {
    const float* dinv = g_ptr[0];
    float* nrm = g_ptr[1];
    int i = blockIdx.x * blockDim.x + threadIdx.x;
    if (i < e) {
        int r = ei[i];
        int c = ei[e + i];
        nrm[i] = dinv[r] * ew[i] * dinv[c];
    }
}

// ---------------------------------------------------------------------------
// GEMM: Y[n,FOUT] = X[n,FIN] @ W[FOUT,FIN]^T   (dot over contiguous dim)
// Block: 64 rows x FOUT cols. 256 threads (16x16), each thread 4 rows x TN.
// srcid >= 0 -> X from scratch slot; else external pointer. Y always scratch.
// ---------------------------------------------------------------------------
template <int FIN, int FOUT, int TN>
__global__ void k_gemm(const float* __restrict__ Xext, int srcid, int dstid,
                       const float* __restrict__ W, int n) {
    const float* X = (srcid >= 0) ? g_ptr[srcid] : Xext;
    float* Y = g_ptr[dstid];

    constexpr int BM = 64, BK = 16;
    __shared__ float As[BM][BK];        // [m][k]
    __shared__ float Bs[BK][FOUT + 1];  // [k][c], +1 pad

    const int tid = threadIdx.x;
    const int tx = tid & 15;   // col group
    const int ty = tid >> 4;   // row group
    const int m0 = blockIdx.x * BM;

    float acc[4][TN];
#pragma unroll
    for (int i = 0; i < 4; i++)
#pragma unroll
        for (int j = 0; j < TN; j++) acc[i][j] = 0.f;

    for (int k0 = 0; k0 < FIN; k0 += BK) {
#pragma unroll
        for (int it = 0; it < (BM * BK) / 256; it++) {
            int idx = it * 256 + tid;
            int m = idx >> 4, k = idx & 15;
            int gr = m0 + m;
            As[m][k] = (gr < n) ? X[(size_t)gr * FIN + k0 + k] : 0.f;
        }
        for (int idx = tid; idx < BK * FOUT; idx += 256) {
            int c = idx >> 4, k = idx & 15;
            Bs[k][c] = W[(size_t)c * FIN + k0 + k];
        }
        __syncthreads();

#pragma unroll
        for (int k = 0; k < BK; k++) {
            float a[4], b[TN];
#pragma unroll
            for (int i = 0; i < 4; i++) a[i] = As[ty * 4 + i][k];
#pragma unroll
            for (int j = 0; j < TN; j++) b[j] = Bs[k][tx * TN + j];
#pragma unroll
            for (int i = 0; i < 4; i++)
#pragma unroll
                for (int j = 0; j < TN; j++) acc[i][j] += a[i] * b[j];
        }
        __syncthreads();
    }

#pragma unroll
    for (int i = 0; i < 4; i++) {
        int gr = m0 + ty * 4 + i;
        if (gr < n) {
#pragma unroll
            for (int j = 0; j < TN; j++)
                Y[(size_t)gr * FOUT + tx * TN + j] = acc[i][j];
        }
    }
}

// ---------------------------------------------------------------------------
// out[i,f] = dinv[i]^2 * xw[i,f] (+ bias[f])  -- self-loop term, full write
// ---------------------------------------------------------------------------
template <int F>
__global__ void k_selfinit(int srcid, int dstid,
                           const float* __restrict__ bias, int n) {
    const float* xw = g_ptr[srcid];
    const float* dinv = g_ptr[0];
    float* out = g_ptr[dstid];

    int idx = blockIdx.x * blockDim.x + threadIdx.x;
    if (idx >= n * F) return;
    int i = idx / F, f = idx % F;
    float d = dinv[i];
    float v = d * d * xw[idx];
    if (bias) v += bias[f];
    out[idx] = v;
}

// ---------------------------------------------------------------------------
// Scatter-add messages: out[col] += norm[e] * xw[row]
// blockDim = (F, 4): one edge per threadIdx.y lane-group, coalesced features.
// ---------------------------------------------------------------------------
template <int F>
__global__ void k_scatter(int srcid, int dstid,
                          const int* __restrict__ ei, int e) {
    const float* xw = g_ptr[srcid];
    const float* nrm = g_ptr[1];
    float* out = g_ptr[dstid];

    int eidx = blockIdx.x * blockDim.y + threadIdx.y;
    if (eidx >= e) return;
    int f = threadIdx.x;
    int r = ei[eidx];
    int c = ei[e + eidx];
    float v = nrm[eidx] * xw[(size_t)r * F + f];
    atomicAdd(out + (size_t)c * F + f, v);
}

// ---------------------------------------------------------------------------
// h = relu( ((agg + b) - m) * rsqrt(v+eps) * g + beta )
// ---------------------------------------------------------------------------
template <int F>
__global__ void k_bnrelu(int srcid, int dstid,
                         const float* __restrict__ b,
                         const float* __restrict__ g,
                         const float* __restrict__ beta,
                         const float* __restrict__ m,
                         const float* __restrict__ v, int n) {
    const float* agg = g_ptr[srcid];
    float* out = g_ptr[dstid];

    int idx = blockIdx.x * blockDim.x + threadIdx.x;
    if (idx >= n * F) return;
    int f = idx % F;
    float inv = rsqrtf(v[f] + BN_EPS);
    float scale = g[f] * inv;
    float t = agg[idx] + b[f];
    float y = (t - m[f]) * scale + beta[f];
    out[idx] = fmaxf(y, 0.f);
}

// Final copy: plain stores into harness-owned d_out (no atomics on d_out).
__global__ void k_copy_out(int srcid, float* __restrict__ out, int total) {
    const float* src = g_ptr[srcid];
    int idx = blockIdx.x * blockDim.x + threadIdx.x;
    if (idx < total) out[idx] = src[idx];
}

// ---------------------------------------------------------------------------
extern "C" void kernel_launch(void* const* d_in, const int* in_sizes, int n_in,
                              void* d_out, int out_size) {
    const float* x = (const float*)d_in[0];
    const int* ei = (const int*)d_in[1];      // int32! (JAX x64 disabled)
    const float* ew = (const float*)d_in[2];
    const float* W1 = (const float*)d_in[3];
    const float* b1 = (const float*)d_in[4];
    const float* W2 = (const float*)d_in[5];
    const float* b2 = (const float*)d_in[6];
    const float* W3 = (const float*)d_in[7];
    const float* b3 = (const float*)d_in[8];
    const float* g1 = (const float*)d_in[9];
    const float* be1 = (const float*)d_in[10];
    const float* m1 = (const float*)d_in[11];
    const float* v1 = (const float*)d_in[12];
    const float* g2 = (const float*)d_in[13];
    const float* be2 = (const float*)d_in[14];
    const float* m2 = (const float*)d_in[15];
    const float* v2 = (const float*)d_in[16];
    float* out = (float*)d_out;

    const int n = in_sizes[0] / 128;
    const int e = in_sizes[2];

    const int TB = 256;
    const int gn = (n + TB - 1) / TB;
    const int ge = (e + TB - 1) / TB;

    // Pointer table (idempotent)
    k_setup<<<1, 1>>>();

    // --- gcn_norm ---
    k_deg_init<<<gn, TB>>>(n);
    k_deg_acc<<<ge, TB>>>(ei, ew, e);
    k_rsqrt_inplace<<<gn, TB>>>(n);
    k_norm<<<ge, TB>>>(ei, ew, e);

    const int gemm_blocks = (n + 63) / 64;
    const int gnf96 = (n * 96 + TB - 1) / TB;
    const int gnf64 = (n * 64 + TB - 1) / TB;
    dim3 sc96(96, 4);
    dim3 sc64(64, 4);
    const int gsc = (e + 3) / 4;

    // Scratch slots: 2 = bufA, 3 = bufB
    // --- Layer 1: 128 -> 96, BN+ReLU ---  (x -> A ; agg in B ; h1 -> A)
    k_gemm<128, 96, 6><<<gemm_blocks, 256>>>(x, -1, 2, W1, n);
    k_selfinit<96><<<gnf96, TB>>>(2, 3, nullptr, n);
    k_scatter<96><<<gsc, sc96>>>(2, 3, ei, e);
    k_bnrelu<96><<<gnf96, TB>>>(3, 2, b1, g1, be1, m1, v1, n);

    // --- Layer 2: 96 -> 96, BN+ReLU ---   (A -> B ; agg in A ; h2 -> B)
    k_gemm<96, 96, 6><<<gemm_blocks, 256>>>(nullptr, 2, 3, W2, n);
    k_selfinit<96><<<gnf96, TB>>>(3, 2, nullptr, n);
    k_scatter<96><<<gsc, sc96>>>(3, 2, ei, e);
    k_bnrelu<96><<<gnf96, TB>>>(2, 3, b2, g2, be2, m2, v2, n);

    // --- Layer 3: 96 -> 64, +bias, no BN --- (B -> A ; agg in B ; copy out)
    k_gemm<96, 64, 4><<<gemm_blocks, 256>>>(nullptr, 3, 2, W3, n);
    k_selfinit<64><<<gnf64, TB>>>(2, 3, b3, n);
    k_scatter<64><<<gsc, sc64>>>(2, 3, ei, e);
    k_copy_out<<<gnf64, TB>>>(3, out, n * 64);
}

// round 14
// speedup vs baseline: 2.9908x; 2.9908x over previous
#include <cuda_runtime.h>
#include <cstddef>

// ---------------------------------------------------------------------------
// GCN_41128606826857: 3-layer GCN, N=50000, E=800000, 128 -> 96 -> 96 -> 64
// edge_index arrives as int32 (JAX x64-disabled demotes int64 -> int32).
//
// Strategy: transform-first (X@W^T), then CSR-gather aggregation (NO atomics
// on feature data), with self-loop + BN+ReLU / bias fused into the gather
// epilogue. CSR built per launch (graph-capture-safe, deterministic work).
// Scratch in __device__ globals accessed via device pointer tables.
// ---------------------------------------------------------------------------

#define NMAX 50000
#define EMAX 800000
#define BN_EPS 1e-5f

__device__ float g_dinv[NMAX];        // degree -> rsqrt(degree)
__device__ float g_bufA[NMAX * 96];
__device__ float g_bufB[NMAX * 96];
__device__ float g_wcsr[EMAX];        // CSR edge norm
__device__ int   g_src[EMAX];         // CSR source node
__device__ int   g_cnt[NMAX];         // in-degree histogram
__device__ int   g_rp[NMAX + 1];      // CSR row_ptr (by target)
__device__ int   g_cur[NMAX];         // fill cursors
__device__ int   g_bsum[256];         // scan block sums

__device__ float* g_ptr[2];           // 0:bufA 1:bufB

__global__ void k_setup() {
    g_ptr[0] = g_bufA;
    g_ptr[1] = g_bufB;
}

// ---------------------------------------------------------------------------
// degree + histogram
// ---------------------------------------------------------------------------
__global__ void k_init_n(int n) {
    int i = blockIdx.x * blockDim.x + threadIdx.x;
    if (i < n) {
        g_dinv[i] = 1.0f;   // self-loop weight
        g_cnt[i] = 0;
    }
}

__global__ void k_hist_deg(const int* __restrict__ ei,
                           const float* __restrict__ ew, int e) {
    int i = blockIdx.x * blockDim.x + threadIdx.x;
    if (i < e) {
        int c = ei[e + i];              // target
        atomicAdd(&g_dinv[c], ew[i]);   // weighted degree
        atomicAdd(&g_cnt[c], 1);        // in-degree count
    }
}

__global__ void k_rsqrt_inplace(int n) {
    int i = blockIdx.x * blockDim.x + threadIdx.x;
    if (i < n) {
        float v = g_dinv[i];
        g_dinv[i] = (v > 0.f) ? rsqrtf(v) : 0.f;
    }
}

// ---------------------------------------------------------------------------
// 2-level exclusive scan of g_cnt -> g_rp (row_ptr), copy to g_cur
// ---------------------------------------------------------------------------
__global__ void k_scan1(int n) {
    __shared__ int s[256];
    int tid = threadIdx.x;
    int i = blockIdx.x * 256 + tid;
    int v = (i < n) ? g_cnt[i] : 0;
    s[tid] = v;
    __syncthreads();
#pragma unroll
    for (int o = 1; o < 256; o <<= 1) {
        int t = (tid >= o) ? s[tid - o] : 0;
        __syncthreads();
        s[tid] += t;
        __syncthreads();
    }
    if (i < n) g_rp[i] = s[tid] - v;          // exclusive within block
    if (tid == 255) g_bsum[blockIdx.x] = s[255];
}

__global__ void k_scan2(int nb) {             // single block; nb <= 256
    __shared__ int s[256];
    int tid = threadIdx.x;
    int v = (tid < nb) ? g_bsum[tid] : 0;
    s[tid] = v;
    __syncthreads();
#pragma unroll
    for (int o = 1; o < 256; o <<= 1) {
        int t = (tid >= o) ? s[tid - o] : 0;
        __syncthreads();
        s[tid] += t;
        __syncthreads();
    }
    if (tid < nb) g_bsum[tid] = s[tid] - v;   // exclusive block offsets
}

__global__ void k_scan3(int n, int e) {
    int i = blockIdx.x * 256 + threadIdx.x;
    if (i < n) {
        int v = g_rp[i] + g_bsum[blockIdx.x];
        g_rp[i] = v;
        g_cur[i] = v;
    }
    if (i == 0) g_rp[n] = e;
}

// ---------------------------------------------------------------------------
// CSR fill: slot per edge under its target; store src + fused edge norm
// ---------------------------------------------------------------------------
__global__ void k_fill(const int* __restrict__ ei,
                       const float* __restrict__ ew, int e) {
    int i = blockIdx.x * blockDim.x + threadIdx.x;
    if (i < e) {
        int r = ei[i];
        int c = ei[e + i];
        int slot = atomicAdd(&g_cur[c], 1);
        g_src[slot] = r;
        g_wcsr[slot] = g_dinv[r] * ew[i] * g_dinv[c];
    }
}

// ---------------------------------------------------------------------------
// GEMM: Y[n,FOUT] = X[n,FIN] @ W[FOUT,FIN]^T
// Block: 64 rows x FOUT cols, 256 threads (16x16), 4 rows x TN cols/thread.
// ---------------------------------------------------------------------------
template <int FIN, int FOUT, int TN>
__global__ void k_gemm(const float* __restrict__ Xext, int srcid, int dstid,
                       const float* __restrict__ W, int n) {
    const float* X = (srcid >= 0) ? g_ptr[srcid] : Xext;
    float* Y = g_ptr[dstid];

    constexpr int BM = 64, BK = 16;
    __shared__ float As[BM][BK];
    __shared__ float Bs[BK][FOUT + 1];

    const int tid = threadIdx.x;
    const int tx = tid & 15;
    const int ty = tid >> 4;
    const int m0 = blockIdx.x * BM;

    float acc[4][TN];
#pragma unroll
    for (int i = 0; i < 4; i++)
#pragma unroll
        for (int j = 0; j < TN; j++) acc[i][j] = 0.f;

    for (int k0 = 0; k0 < FIN; k0 += BK) {
#pragma unroll
        for (int it = 0; it < (BM * BK) / 256; it++) {
            int idx = it * 256 + tid;
            int m = idx >> 4, k = idx & 15;
            int gr = m0 + m;
            As[m][k] = (gr < n) ? X[(size_t)gr * FIN + k0 + k] : 0.f;
        }
        for (int idx = tid; idx < BK * FOUT; idx += 256) {
            int c = idx >> 4, k = idx & 15;
            Bs[k][c] = W[(size_t)c * FIN + k0 + k];
        }
        __syncthreads();

#pragma unroll
        for (int k = 0; k < BK; k++) {
            float a[4], b[TN];
#pragma unroll
            for (int i = 0; i < 4; i++) a[i] = As[ty * 4 + i][k];
#pragma unroll
            for (int j = 0; j < TN; j++) b[j] = Bs[k][tx * TN + j];
#pragma unroll
            for (int i = 0; i < 4; i++)
#pragma unroll
                for (int j = 0; j < TN; j++) acc[i][j] += a[i] * b[j];
        }
        __syncthreads();
    }

#pragma unroll
    for (int i = 0; i < 4; i++) {
        int gr = m0 + ty * 4 + i;
        if (gr < n) {
#pragma unroll
            for (int j = 0; j < TN; j++)
                Y[(size_t)gr * FOUT + tx * TN + j] = acc[i][j];
        }
    }
}

// ---------------------------------------------------------------------------
// Fused gather-aggregate + epilogue. One (node, feat) per thread.
// acc = dinv[i]^2 * xw[i,f] + sum_{k in CSR[i]} wcsr[k] * xw[src[k], f]
// BN=true : out = relu((acc + b - m) * g * rsqrt(v+eps) + beta)  -> scratch
// BN=false: out = acc + b                                        -> external
// Each output written exactly once by plain store (d_out-safe, no atomics).
// ---------------------------------------------------------------------------
template <int F, bool BN>
__global__ void k_agg(int srcid, int dstid, float* __restrict__ Oext,
                      const float* __restrict__ b,
                      const float* __restrict__ g,
                      const float* __restrict__ be,
                      const float* __restrict__ m,
                      const float* __restrict__ v, int n) {
    const float* xw = g_ptr[srcid];
    float* out = (dstid >= 0) ? g_ptr[dstid] : Oext;

    int i = blockIdx.x * blockDim.y + threadIdx.y;
    if (i >= n) return;
    int f = threadIdx.x;

    float di = g_dinv[i];
    float acc = di * di * xw[(size_t)i * F + f];

    int k0 = g_rp[i], k1 = g_rp[i + 1];
    for (int k = k0; k < k1; k++) {
        int s = g_src[k];
        float w = g_wcsr[k];
        acc += w * xw[(size_t)s * F + f];
    }

    if (BN) {
        float inv = rsqrtf(v[f] + BN_EPS);
        float y = (acc + b[f] - m[f]) * (g[f] * inv) + be[f];
        out[(size_t)i * F + f] = fmaxf(y, 0.f);
    } else {
        out[(size_t)i * F + f] = acc + b[f];
    }
}

// ---------------------------------------------------------------------------
extern "C" void kernel_launch(void* const* d_in, const int* in_sizes, int n_in,
                              void* d_out, int out_size) {
    const float* x = (const float*)d_in[0];
    const int* ei = (const int*)d_in[1];      // int32 (JAX x64 disabled)
    const float* ew = (const float*)d_in[2];
    const float* W1 = (const float*)d_in[3];
    const float* b1 = (const float*)d_in[4];
    const float* W2 = (const float*)d_in[5];
    const float* b2 = (const float*)d_in[6];
    const float* W3 = (const float*)d_in[7];
    const float* b3 = (const float*)d_in[8];
    const float* g1 = (const float*)d_in[9];
    const float* be1 = (const float*)d_in[10];
    const float* m1 = (const float*)d_in[11];
    const float* v1 = (const float*)d_in[12];
    const float* g2 = (const float*)d_in[13];
    const float* be2 = (const float*)d_in[14];
    const float* m2 = (const float*)d_in[15];
    const float* v2 = (const float*)d_in[16];
    float* out = (float*)d_out;

    const int n = in_sizes[0] / 128;
    const int e = in_sizes[2];

    const int TB = 256;
    const int gn = (n + TB - 1) / TB;     // 196 for n=50000
    const int ge = (e + TB - 1) / TB;

    k_setup<<<1, 1>>>();

    // --- degree / histogram / CSR build ---
    k_init_n<<<gn, TB>>>(n);
    k_hist_deg<<<ge, TB>>>(ei, ew, e);
    k_rsqrt_inplace<<<gn, TB>>>(n);
    k_scan1<<<gn, 256>>>(n);
    k_scan2<<<1, 256>>>(gn);
    k_scan3<<<gn, 256>>>(n, e);
    k_fill<<<ge, TB>>>(ei, ew, e);

    const int gemm_blocks = (n + 63) / 64;
    const int agg_blocks = (n + 3) / 4;
    dim3 agg96(96, 4);
    dim3 agg64(64, 4);

    // Scratch slots: 0 = bufA, 1 = bufB
    // --- Layer 1: 128 -> 96, agg + BN + ReLU ---   (x -> A ; h1 -> B)
    k_gemm<128, 96, 6><<<gemm_blocks, 256>>>(x, -1, 0, W1, n);
    k_agg<96, true><<<agg_blocks, agg96>>>(0, 1, nullptr, b1, g1, be1, m1, v1, n);

    // --- Layer 2: 96 -> 96, agg + BN + ReLU ---    (B -> A ; h2 -> B)
    k_gemm<96, 96, 6><<<gemm_blocks, 256>>>(nullptr, 1, 0, W2, n);
    k_agg<96, true><<<agg_blocks, agg96>>>(0, 1, nullptr, b2, g2, be2, m2, v2, n);

    // --- Layer 3: 96 -> 64, agg + bias -> d_out --- (B -> A ; out ext)
    k_gemm<96, 64, 4><<<gemm_blocks, 256>>>(nullptr, 1, 0, W3, n);
    k_agg<64, false><<<agg_blocks, agg64>>>(0, -1, out, b3, nullptr, nullptr, nullptr, nullptr, n);
}

// round 17
// speedup vs baseline: 3.5823x; 1.1978x over previous
#include <cuda_runtime.h>
#include <cstddef>
#include <cstdint>

// ---------------------------------------------------------------------------
// GCN_41128606826857: 3-layer GCN, N=50000, E=800000, 128 -> 96 -> 96 -> 64
// edge_index arrives as int32 (JAX x64-disabled demotes int64 -> int32).
//
// transform-first (X@W^T) with 3xTF32 tensor-core GEMM (fp32-class accuracy),
// then CSR-gather aggregation (no atomics on feature data) with self-loop +
// BN+ReLU / bias fused into the gather epilogue. CSR built per launch.
// ---------------------------------------------------------------------------

#define NMAX 50000
#define EMAX 800000
#define BN_EPS 1e-5f

__device__ float g_dinv[NMAX];        // degree -> rsqrt(degree)
__device__ float g_bufA[NMAX * 96];
__device__ float g_bufB[NMAX * 96];
__device__ float g_wcsr[EMAX];        // CSR edge norm
__device__ int   g_src[EMAX];         // CSR source node
__device__ int   g_cnt[NMAX];         // in-degree histogram
__device__ int   g_rp[NMAX + 1];      // CSR row_ptr (by target)
__device__ int   g_cur[NMAX];         // fill cursors
__device__ int   g_bsum[256];         // scan block sums

__device__ float* g_ptr[2];           // 0:bufA 1:bufB

__global__ void k_setup() {
    g_ptr[0] = g_bufA;
    g_ptr[1] = g_bufB;
}

// ---------------------------------------------------------------------------
// degree + histogram
// ---------------------------------------------------------------------------
__global__ void k_init_n(int n) {
    int i = blockIdx.x * blockDim.x + threadIdx.x;
    if (i < n) {
        g_dinv[i] = 1.0f;   // self-loop weight
        g_cnt[i] = 0;
    }
}

__global__ void k_hist_deg(const int* __restrict__ ei,
                           const float* __restrict__ ew, int e) {
    int i = blockIdx.x * blockDim.x + threadIdx.x;
    if (i < e) {
        int c = ei[e + i];              // target
        atomicAdd(&g_dinv[c], ew[i]);   // weighted degree
        atomicAdd(&g_cnt[c], 1);        // in-degree count
    }
}

__global__ void k_rsqrt_inplace(int n) {
    int i = blockIdx.x * blockDim.x + threadIdx.x;
    if (i < n) {
        float v = g_dinv[i];
        g_dinv[i] = (v > 0.f) ? rsqrtf(v) : 0.f;
    }
}

// ---------------------------------------------------------------------------
// 2-level exclusive scan of g_cnt -> g_rp (row_ptr), copy to g_cur
// ---------------------------------------------------------------------------
__global__ void k_scan1(int n) {
    __shared__ int s[256];
    int tid = threadIdx.x;
    int i = blockIdx.x * 256 + tid;
    int v = (i < n) ? g_cnt[i] : 0;
    s[tid] = v;
    __syncthreads();
#pragma unroll
    for (int o = 1; o < 256; o <<= 1) {
        int t = (tid >= o) ? s[tid - o] : 0;
        __syncthreads();
        s[tid] += t;
        __syncthreads();
    }
    if (i < n) g_rp[i] = s[tid] - v;
    if (tid == 255) g_bsum[blockIdx.x] = s[255];
}

__global__ void k_scan2(int nb) {             // single block; nb <= 256
    __shared__ int s[256];
    int tid = threadIdx.x;
    int v = (tid < nb) ? g_bsum[tid] : 0;
    s[tid] = v;
    __syncthreads();
#pragma unroll
    for (int o = 1; o < 256; o <<= 1) {
        int t = (tid >= o) ? s[tid - o] : 0;
        __syncthreads();
        s[tid] += t;
        __syncthreads();
    }
    if (tid < nb) g_bsum[tid] = s[tid] - v;
}

__global__ void k_scan3(int n, int e) {
    int i = blockIdx.x * 256 + threadIdx.x;
    if (i < n) {
        int v = g_rp[i] + g_bsum[blockIdx.x];
        g_rp[i] = v;
        g_cur[i] = v;
    }
    if (i == 0) g_rp[n] = e;
}

__global__ void k_fill(const int* __restrict__ ei,
                       const float* __restrict__ ew, int e) {
    int i = blockIdx.x * blockDim.x + threadIdx.x;
    if (i < e) {
        int r = ei[i];
        int c = ei[e + i];
        int slot = atomicAdd(&g_cur[c], 1);
        g_src[slot] = r;
        g_wcsr[slot] = g_dinv[r] * ew[i] * g_dinv[c];
    }
}

// ---------------------------------------------------------------------------
// 3xTF32 tensor-core GEMM: Y[n,FOUT] = X[n,FIN] @ W[FOUT,FIN]^T
// Block 256 thr (8 warps), BM=128 (16 rows/warp), BK=16.
// Each operand split x = hi + lo (tf32 + residual); acc += Ah*Bh + Ah*Bl + Al*Bh.
// ---------------------------------------------------------------------------
__device__ __forceinline__ uint32_t cvt_tf32(float x) {
    uint32_t u;
    asm("cvt.rna.tf32.f32 %0, %1;" : "=r"(u) : "f"(x));
    return u;
}

#define MMA_TF32(c, a0, a1, a2, a3, b0, b1)                                   \
    asm volatile(                                                             \
        "mma.sync.aligned.m16n8k8.row.col.f32.tf32.tf32.f32 "                 \
        "{%0,%1,%2,%3}, {%4,%5,%6,%7}, {%8,%9}, {%0,%1,%2,%3};"               \
        : "+f"(c[0]), "+f"(c[1]), "+f"(c[2]), "+f"(c[3])                      \
        : "r"(a0), "r"(a1), "r"(a2), "r"(a3), "r"(b0), "r"(b1))

template <int FIN, int FOUT>
__global__ __launch_bounds__(256) void k_gemm_tc(const float* __restrict__ Xext,
                                                 int srcid, int dstid,
                                                 float* __restrict__ Oext,
                                                 const float* __restrict__ W,
                                                 int n) {
    const float* X = (srcid >= 0) ? g_ptr[srcid] : Xext;
    float* Y = (dstid >= 0) ? g_ptr[dstid] : Oext;

    constexpr int BM = 128, BK = 16, SK = BK + 4;  // stride 20: conflict-free
    constexpr int NT = FOUT / 8;

    __shared__ float Ah[BM * SK], Al[BM * SK];
    __shared__ float Bh[FOUT * SK], Bl[FOUT * SK];

    const int tid = threadIdx.x;
    const int w = tid >> 5, l = tid & 31;
    const int g = l >> 2, tg = l & 3;
    const int m0 = blockIdx.x * BM;

    float c[NT][4];
#pragma unroll
    for (int t = 0; t < NT; t++)
#pragma unroll
        for (int j = 0; j < 4; j++) c[t][j] = 0.f;

    for (int k0 = 0; k0 < FIN; k0 += BK) {
        // ---- load + split A tile: BM x BK (BM*4 float4 = 512 -> 2/thread)
#pragma unroll
        for (int it = 0; it < (BM * 4) / 256; it++) {
            int idx = it * 256 + tid;
            int r = idx >> 2, f4 = (idx & 3) * 4;
            float4 v = make_float4(0.f, 0.f, 0.f, 0.f);
            if (m0 + r < n)
                v = *(const float4*)&X[(size_t)(m0 + r) * FIN + k0 + f4];
            float h0 = __uint_as_float(cvt_tf32(v.x));
            float h1 = __uint_as_float(cvt_tf32(v.y));
            float h2 = __uint_as_float(cvt_tf32(v.z));
            float h3 = __uint_as_float(cvt_tf32(v.w));
            float* ah = &Ah[r * SK + f4];
            float* al = &Al[r * SK + f4];
            ah[0] = h0; ah[1] = h1; ah[2] = h2; ah[3] = h3;
            al[0] = __uint_as_float(cvt_tf32(v.x - h0));
            al[1] = __uint_as_float(cvt_tf32(v.y - h1));
            al[2] = __uint_as_float(cvt_tf32(v.z - h2));
            al[3] = __uint_as_float(cvt_tf32(v.w - h3));
        }
        // ---- load + split B tile: FOUT x BK
        for (int idx = tid; idx < FOUT * 4; idx += 256) {
            int r = idx >> 2, f4 = (idx & 3) * 4;
            float4 v = *(const float4*)&W[(size_t)r * FIN + k0 + f4];
            float h0 = __uint_as_float(cvt_tf32(v.x));
            float h1 = __uint_as_float(cvt_tf32(v.y));
            float h2 = __uint_as_float(cvt_tf32(v.z));
            float h3 = __uint_as_float(cvt_tf32(v.w));
            float* bh = &Bh[r * SK + f4];
            float* bl = &Bl[r * SK + f4];
            bh[0] = h0; bh[1] = h1; bh[2] = h2; bh[3] = h3;
            bl[0] = __uint_as_float(cvt_tf32(v.x - h0));
            bl[1] = __uint_as_float(cvt_tf32(v.y - h1));
            bl[2] = __uint_as_float(cvt_tf32(v.z - h2));
            bl[3] = __uint_as_float(cvt_tf32(v.w - h3));
        }
        __syncthreads();

#pragma unroll
        for (int ks = 0; ks < BK; ks += 8) {
            const int ar0 = (w * 16 + g) * SK + ks;
            const int ar1 = (w * 16 + g + 8) * SK + ks;
            uint32_t ah0 = __float_as_uint(Ah[ar0 + tg]);
            uint32_t ah1 = __float_as_uint(Ah[ar1 + tg]);
            uint32_t ah2 = __float_as_uint(Ah[ar0 + tg + 4]);
            uint32_t ah3 = __float_as_uint(Ah[ar1 + tg + 4]);
            uint32_t al0 = __float_as_uint(Al[ar0 + tg]);
            uint32_t al1 = __float_as_uint(Al[ar1 + tg]);
            uint32_t al2 = __float_as_uint(Al[ar0 + tg + 4]);
            uint32_t al3 = __float_as_uint(Al[ar1 + tg + 4]);
#pragma unroll
            for (int nt = 0; nt < NT; nt++) {
                const int br = (nt * 8 + g) * SK + ks;
                uint32_t bh0 = __float_as_uint(Bh[br + tg]);
                uint32_t bh1 = __float_as_uint(Bh[br + tg + 4]);
                uint32_t bl0 = __float_as_uint(Bl[br + tg]);
                uint32_t bl1 = __float_as_uint(Bl[br + tg + 4]);
                MMA_TF32(c[nt], ah0, ah1, ah2, ah3, bh0, bh1);
                MMA_TF32(c[nt], ah0, ah1, ah2, ah3, bl0, bl1);
                MMA_TF32(c[nt], al0, al1, al2, al3, bh0, bh1);
            }
        }
        __syncthreads();
    }

    // ---- store C: rows (g, g+8), cols (2tg, 2tg+1) per n-tile
    const int r0 = m0 + w * 16 + g;
    const int r1 = r0 + 8;
#pragma unroll
    for (int nt = 0; nt < NT; nt++) {
        int col = nt * 8 + 2 * tg;
        if (r0 < n)
            *(float2*)&Y[(size_t)r0 * FOUT + col] = make_float2(c[nt][0], c[nt][1]);
        if (r1 < n)
            *(float2*)&Y[(size_t)r1 * FOUT + col] = make_float2(c[nt][2], c[nt][3]);
    }
}

// ---------------------------------------------------------------------------
// Fused gather-aggregate + epilogue. One (node, feat) per thread.
// acc = dinv[i]^2 * xw[i,f] + sum_{k in CSR[i]} wcsr[k] * xw[src[k], f]
// BN=true : out = relu((acc + b - m) * g * rsqrt(v+eps) + beta)  -> scratch
// BN=false: out = acc + b                                        -> external
// ---------------------------------------------------------------------------
template <int F, bool BN>
__global__ void k_agg(int srcid, int dstid, float* __restrict__ Oext,
                      const float* __restrict__ b,
                      const float* __restrict__ g,
                      const float* __restrict__ be,
                      const float* __restrict__ m,
                      const float* __restrict__ v, int n) {
    const float* xw = g_ptr[srcid];
    float* out = (dstid >= 0) ? g_ptr[dstid] : Oext;

    int i = blockIdx.x * blockDim.y + threadIdx.y;
    if (i >= n) return;
    int f = threadIdx.x;

    float di = g_dinv[i];
    float acc = di * di * xw[(size_t)i * F + f];

    int k0 = g_rp[i], k1 = g_rp[i + 1];
    for (int k = k0; k < k1; k++) {
        int s = g_src[k];
        float w = g_wcsr[k];
        acc += w * xw[(size_t)s * F + f];
    }

    if (BN) {
        float inv = rsqrtf(v[f] + BN_EPS);
        float y = (acc + b[f] - m[f]) * (g[f] * inv) + be[f];
        out[(size_t)i * F + f] = fmaxf(y, 0.f);
    } else {
        out[(size_t)i * F + f] = acc + b[f];
    }
}

// ---------------------------------------------------------------------------
extern "C" void kernel_launch(void* const* d_in, const int* in_sizes, int n_in,
                              void* d_out, int out_size) {
    const float* x = (const float*)d_in[0];
    const int* ei = (const int*)d_in[1];      // int32 (JAX x64 disabled)
    const float* ew = (const float*)d_in[2];
    const float* W1 = (const float*)d_in[3];
    const float* b1 = (const float*)d_in[4];
    const float* W2 = (const float*)d_in[5];
    const float* b2 = (const float*)d_in[6];
    const float* W3 = (const float*)d_in[7];
    const float* b3 = (const float*)d_in[8];
    const float* g1 = (const float*)d_in[9];
    const float* be1 = (const float*)d_in[10];
    const float* m1 = (const float*)d_in[11];
    const float* v1 = (const float*)d_in[12];
    const float* g2 = (const float*)d_in[13];
    const float* be2 = (const float*)d_in[14];
    const float* m2 = (const float*)d_in[15];
    const float* v2 = (const float*)d_in[16];
    float* out = (float*)d_out;

    const int n = in_sizes[0] / 128;
    const int e = in_sizes[2];

    const int TB = 256;
    const int gn = (n + TB - 1) / TB;     // 196 blocks (<= 256 for scan2)
    const int ge = (e + TB - 1) / TB;

    k_setup<<<1, 1>>>();

    // --- degree / histogram / CSR build ---
    k_init_n<<<gn, TB>>>(n);
    k_hist_deg<<<ge, TB>>>(ei, ew, e);
    k_rsqrt_inplace<<<gn, TB>>>(n);
    k_scan1<<<gn, 256>>>(n);
    k_scan2<<<1, 256>>>(gn);
    k_scan3<<<gn, 256>>>(n, e);
    k_fill<<<ge, TB>>>(ei, ew, e);

    const int gemm_blocks = (n + 127) / 128;
    const int agg_blocks = (n + 3) / 4;
    dim3 agg96(96, 4);
    dim3 agg64(64, 4);

    // Scratch slots: 0 = bufA, 1 = bufB
    // --- Layer 1: 128 -> 96, agg + BN + ReLU ---   (x -> A ; h1 -> B)
    k_gemm_tc<128, 96><<<gemm_blocks, 256>>>(x, -1, 0, nullptr, W1, n);
    k_agg<96, true><<<agg_blocks, agg96>>>(0, 1, nullptr, b1, g1, be1, m1, v1, n);

    // --- Layer 2: 96 -> 96, agg + BN + ReLU ---    (B -> A ; h2 -> B)
    k_gemm_tc<96, 96><<<gemm_blocks, 256>>>(nullptr, 1, 0, nullptr, W2, n);
    k_agg<96, true><<<agg_blocks, agg96>>>(0, 1, nullptr, b2, g2, be2, m2, v2, n);

    // --- Layer 3: 96 -> 64, agg + bias -> d_out --- (B -> A ; out ext)
    k_gemm_tc<96, 64><<<gemm_blocks, 256>>>(nullptr, 1, 0, nullptr, W3, n);
    k_agg<64, false><<<agg_blocks, agg64>>>(0, -1, out, b3, nullptr, nullptr, nullptr, nullptr, n);
}